// round 8
// baseline (speedup 1.0000x reference)
#include <cuda_runtime.h>
#include <cuda_bf16.h>
#include <math.h>
#include <stdint.h>

#define B_SZ 1024
#define LATD 64
#define FCON 256
#define IN0  320
#define HIDD 512
#define INTER 576
#define NOUT 512
#define NE   8
#define GH   64
#define K0P  2624   // 8*320+64 (bias tail)
#define K1P  4672   // 8*576+64

__device__ float g_coeff[B_SZ*NE];
__device__ float g_p0[B_SZ*NOUT];
__device__ float g_p1[B_SZ*NOUT];
__device__ float g_p2[B_SZ*NOUT];
__device__ float g_p3[B_SZ*NOUT];
__device__ __nv_bfloat16 g_Ahi[B_SZ*K1P];
__device__ __nv_bfloat16 g_Alo[B_SZ*K1P];
__device__ __nv_bfloat16 g_W0hi[NOUT*K0P];
__device__ __nv_bfloat16 g_W0lo[NOUT*K0P];
__device__ __nv_bfloat16 g_W1hi[NOUT*K1P];
__device__ __nv_bfloat16 g_W1lo[NOUT*K1P];
__device__ __nv_bfloat16 g_W2hi[NOUT*K1P];
__device__ __nv_bfloat16 g_W2lo[NOUT*K1P];

__device__ __forceinline__ float elu_f(float x){ return x > 0.0f ? x : expm1f(x); }

__device__ __forceinline__ uint32_t smem_u32(const void* p){
    uint32_t a;
    asm("{ .reg .u64 t; cvta.to.shared.u64 t, %1; cvt.u32.u64 %0, t; }" : "=r"(a) : "l"(p));
    return a;
}

#define CP16(s, g) asm volatile("cp.async.cg.shared.global [%0], [%1], 16;" :: "r"(s), "l"(g))
#define CP_COMMIT() asm volatile("cp.async.commit_group;" ::: "memory")
#define CP_WAIT0()  asm volatile("cp.async.wait_group 0;" ::: "memory")

#define LDSM4(r0,r1,r2,r3,addr) \
    asm volatile("ldmatrix.sync.aligned.m8n8.x4.shared.b16 {%0,%1,%2,%3}, [%4];" \
        : "=r"(r0), "=r"(r1), "=r"(r2), "=r"(r3) : "r"(addr))

#define MMA16816(c, a0,a1,a2,a3, b0,b1) \
    asm volatile("mma.sync.aligned.m16n8k16.row.col.f32.bf16.bf16.f32 " \
        "{%0,%1,%2,%3}, {%4,%5,%6,%7}, {%8,%9}, {%0,%1,%2,%3};" \
        : "+f"((c)[0]), "+f"((c)[1]), "+f"((c)[2]), "+f"((c)[3]) \
        : "r"(a0), "r"(a1), "r"(a2), "r"(a3), "r"(b0), "r"(b1))

__device__ __forceinline__ void split_pair(float a, float b, uint32_t& h, uint32_t& l){
    __nv_bfloat16 ha = __float2bfloat16_rn(a), hb = __float2bfloat16_rn(b);
    __nv_bfloat16 la = __float2bfloat16_rn(a - __bfloat162float(ha));
    __nv_bfloat16 lb = __float2bfloat16_rn(b - __bfloat162float(hb));
    __nv_bfloat162 H = __halves2bfloat162(ha, hb), L = __halves2bfloat162(la, lb);
    h = *reinterpret_cast<uint32_t*>(&H); l = *reinterpret_cast<uint32_t*>(&L);
}

// ------- fused: (z<3) weight transpose + bias tail; (z==3) gate + layer-0 A' -------
__global__ void pre_kernel(
    const float* __restrict__ w0, const float* __restrict__ b0,
    const float* __restrict__ w1, const float* __restrict__ b1,
    const float* __restrict__ w2, const float* __restrict__ b2,
    const float* __restrict__ z,  const float* __restrict__ c,
    const float* __restrict__ gw1, const float* __restrict__ gb1,
    const float* __restrict__ gw2, const float* __restrict__ gb2,
    const float* __restrict__ gw3, const float* __restrict__ gb3)
{
    __shared__ float tile[32][33];
    __shared__ float x[IN0], h1[GH], h2[GH], lg[NE], cf[NE];

    if (blockIdx.z < 3){
        const float *W, *bias; __nv_bfloat16 *Whi, *Wlo; int KTOT, KP;
        if (blockIdx.z == 0){ W=w0; bias=b0; Whi=g_W0hi; Wlo=g_W0lo; KTOT=NE*IN0;   KP=K0P; }
        else if (blockIdx.z == 1){ W=w1; bias=b1; Whi=g_W1hi; Wlo=g_W1lo; KTOT=NE*INTER; KP=K1P; }
        else { W=w2; bias=b2; Whi=g_W2hi; Wlo=g_W2lo; KTOT=NE*INTER; KP=K1P; }

        int k0 = blockIdx.x*32;
        if (k0 >= KP) return;
        int n0 = blockIdx.y*32;
        int xx = threadIdx.x, yy = threadIdx.y;

        if (k0 < KTOT){
            #pragma unroll
            for (int j = 0; j < 32; j += 8)
                tile[yy+j][xx] = W[(size_t)(k0+yy+j)*NOUT + n0 + xx];
            __syncthreads();
            #pragma unroll
            for (int j = 0; j < 32; j += 8){
                float v = tile[xx][yy+j];
                int n = n0+yy+j, k = k0+xx;
                __nv_bfloat16 h = __float2bfloat16_rn(v);
                __nv_bfloat16 l = __float2bfloat16_rn(v - __bfloat162float(h));
                Whi[(size_t)n*KP + k] = h; Wlo[(size_t)n*KP + k] = l;
            }
        } else {
            int k = k0 + xx, j = k - KTOT;
            #pragma unroll
            for (int r = 0; r < 32; r += 8){
                int n = n0 + yy + r;
                float v = (j < NE) ? bias[j*NOUT + n] : 0.0f;
                __nv_bfloat16 h = __float2bfloat16_rn(v);
                __nv_bfloat16 l = __float2bfloat16_rn(v - __bfloat162float(h));
                Whi[(size_t)n*KP + k] = h; Wlo[(size_t)n*KP + k] = l;
            }
        }
        return;
    }

    // z == 3: gate + layer-0 A'
    int id = blockIdx.y*gridDim.x + blockIdx.x;
    if (id >= B_SZ) return;
    int b = id;
    int tid = threadIdx.y*32 + threadIdx.x;

    if (tid < LATD) x[tid] = z[b*LATD + tid];
    for (int i = tid; i < FCON; i += 256) x[LATD+i] = c[b*FCON + i];
    __syncthreads();

    if (tid < GH){
        float acc = gb1[tid];
        #pragma unroll 8
        for (int i = 0; i < IN0; i++) acc += x[i]*gw1[i*GH + tid];
        h1[tid] = elu_f(acc);
    }
    __syncthreads();
    if (tid < GH){
        float acc = gb2[tid];
        #pragma unroll 8
        for (int i = 0; i < GH; i++) acc += h1[i]*gw2[i*GH + tid];
        h2[tid] = elu_f(acc);
    }
    __syncthreads();
    if (tid < NE){
        float a = gb3[tid];
        #pragma unroll 8
        for (int i = 0; i < GH; i++) a += h2[i]*gw3[i*NE + tid];
        lg[tid] = a;
    }
    __syncthreads();
    if (tid < NE){
        float m = lg[0];
        #pragma unroll
        for (int i = 1; i < NE; i++) m = fmaxf(m, lg[i]);
        float s = 0.f;
        #pragma unroll
        for (int i = 0; i < NE; i++) s += expf(lg[i]-m);
        float cv = expf(lg[tid]-m)/s;
        cf[tid] = cv;
        g_coeff[b*NE + tid] = cv;
    }
    __syncthreads();

    uint4* oh = (uint4*)(g_Ahi + (size_t)b*K0P);
    uint4* ol = (uint4*)(g_Alo + (size_t)b*K0P);
    const int inu = IN0 >> 3, main_u = NE*inu, NU = K0P >> 3;
    for (int u = tid; u < NU; u += 256){
        float v[8];
        if (u < main_u){
            int e = u/inu, i8 = (u - e*inu) << 3;
            float s = cf[e];
            #pragma unroll
            for (int l = 0; l < 8; l++) v[l] = x[i8+l]*s;
        } else {
            int j = (u - main_u) << 3;
            #pragma unroll
            for (int l = 0; l < 8; l++) v[l] = (j+l < NE) ? cf[j+l] : 0.0f;
        }
        uint4 hh, ll;
        split_pair(v[0],v[1],hh.x,ll.x); split_pair(v[2],v[3],hh.y,ll.y);
        split_pair(v[4],v[5],hh.z,ll.z); split_pair(v[6],v[7],hh.w,ll.w);
        oh[u] = hh; ol[u] = ll;
    }
}

// ------- A' build for layers 1/2: prev = elu(p0+p1+p2+p3) inline -------
__global__ __launch_bounds__(256) void prep_combine_kernel(
    const float* __restrict__ z,
    const float* __restrict__ p0, const float* __restrict__ p1,
    const float* __restrict__ p2, const float* __restrict__ p3,
    __nv_bfloat16* __restrict__ Ahi, __nv_bfloat16* __restrict__ Alo)
{
    constexpr int IN = INTER, KP = K1P;
    int b = blockIdx.x, tid = threadIdx.x;
    __shared__ float cf[NE];
    __shared__ float xp[HIDD];
    if (tid < NE) cf[tid] = g_coeff[b*NE + tid];
    {
        const float4* a4 = (const float4*)(p0 + (size_t)b*NOUT);
        const float4* b4 = (const float4*)(p1 + (size_t)b*NOUT);
        const float4* c4 = (const float4*)(p2 + (size_t)b*NOUT);
        const float4* d4 = (const float4*)(p3 + (size_t)b*NOUT);
        float4* x4 = (float4*)xp;
        for (int i = tid; i < HIDD/4; i += 256){
            float4 u = a4[i], w = b4[i], s = c4[i], t = d4[i];
            float4 r;
            r.x = elu_f(u.x + w.x + s.x + t.x); r.y = elu_f(u.y + w.y + s.y + t.y);
            r.z = elu_f(u.z + w.z + s.z + t.z); r.w = elu_f(u.w + w.w + s.w + t.w);
            x4[i] = r;
        }
    }
    __syncthreads();

    const float4* z4 = (const float4*)(z + (size_t)b*LATD);
    uint4* oh = (uint4*)(Ahi + (size_t)b*KP);
    uint4* ol = (uint4*)(Alo + (size_t)b*KP);
    const int inu = IN >> 3, main_u = NE*inu, NU = KP >> 3;
    for (int u = tid; u < NU; u += 256){
        float v[8];
        if (u < main_u){
            int e = u/inu, i8 = (u - e*inu) << 3;
            float s = cf[e];
            if (i8 < LATD){
                float4 x0 = z4[i8>>2], x1 = z4[(i8>>2)+1];
                v[0]=x0.x*s; v[1]=x0.y*s; v[2]=x0.z*s; v[3]=x0.w*s;
                v[4]=x1.x*s; v[5]=x1.y*s; v[6]=x1.z*s; v[7]=x1.w*s;
            } else {
                int q = i8 - LATD;
                #pragma unroll
                for (int l = 0; l < 8; l++) v[l] = xp[q+l]*s;
            }
        } else {
            int j = (u - main_u) << 3;
            #pragma unroll
            for (int l = 0; l < 8; l++) v[l] = (j+l < NE) ? cf[j+l] : 0.0f;
        }
        uint4 hh, ll;
        split_pair(v[0],v[1],hh.x,ll.x); split_pair(v[2],v[3],hh.y,ll.y);
        split_pair(v[4],v[5],hh.z,ll.z); split_pair(v[6],v[7],hh.w,ll.w);
        oh[u] = hh; ol[u] = ll;
    }
}

// ------- final combine: out = p0+p1+p2+p3 -------
__global__ __launch_bounds__(256) void combine_kernel(
    const float* __restrict__ p0, const float* __restrict__ p1,
    const float* __restrict__ p2, const float* __restrict__ p3, float* __restrict__ out)
{
    int i = blockIdx.x*256 + threadIdx.x;
    const float4* a4 = (const float4*)p0;
    const float4* b4 = (const float4*)p1;
    const float4* c4 = (const float4*)p2;
    const float4* d4 = (const float4*)p3;
    float4* o4 = (float4*)out;
    float4 u = a4[i], w = b4[i], s = c4[i], t = d4[i];
    float4 r;
    r.x = u.x+w.x+s.x+t.x; r.y = u.y+w.y+s.y+t.y;
    r.z = u.z+w.z+s.z+t.z; r.w = u.w+w.w+s.w+t.w;
    o4[i] = r;
}

// ------- GEMM: CTA 128x64, warp tile 32x32 (4m x 2n), split-K=4, 2-stage cp.async -------
// Stage (48KB): AH@0(16K) AL@16384 BH@32768(8K) BL@40960; 2 stages = 96KB.
#define STG_SZ 49152
#define GSMEM (2*STG_SZ)

template<int KTOT>
__global__ __launch_bounds__(256, 2) void gemm_kernel(
    const __nv_bfloat16* __restrict__ Ahi, const __nv_bfloat16* __restrict__ Alo,
    const __nv_bfloat16* __restrict__ Whi, const __nv_bfloat16* __restrict__ Wlo,
    float* __restrict__ p0, float* __restrict__ p1,
    float* __restrict__ p2, float* __restrict__ p3)
{
    constexpr int KP = KTOT*64;
    constexpr int q = KTOT/4, rr = KTOT%4;
    extern __shared__ char smem[];
    const uint32_t sb = smem_u32(smem);
    const int tid = threadIdx.x, wid = tid >> 5, L = tid & 31;
    const int m0 = blockIdx.y*128, n0 = blockIdx.x*64;
    const int wm = (wid & 3)*32, wn = (wid >> 2)*32;
    const int zz = blockIdx.z;
    const int KT = q + (zz < rr ? 1 : 0);
    const int t0 = zz*q + (zz < rr ? zz : rr);
    float* part = (zz == 0) ? p0 : (zz == 1) ? p1 : (zz == 2) ? p2 : p3;

    // loaders: A rows 0..127 (4 passes), B rows 0..63 (2 passes)
    uint32_t s_o[4];
    const __nv_bfloat16 *gah[4], *gal[4], *gbh[2], *gbl[2];
    #pragma unroll
    for (int r = 0; r < 4; r++){
        int ch = tid + r*256, row = ch >> 3, kc = ch & 7;
        s_o[r] = row*128 + ((kc*16) ^ ((row & 7) << 4));
        size_t kb0 = (size_t)t0*64 + kc*8;
        gah[r] = Ahi + (size_t)(m0+row)*KP + kb0;
        gal[r] = Alo + (size_t)(m0+row)*KP + kb0;
        if (r < 2){
            gbh[r] = Whi + (size_t)(n0+row)*KP + kb0;
            gbl[r] = Wlo + (size_t)(n0+row)*KP + kb0;
        }
    }

    const int alf = (L & 7) + ((L >> 3) & 1)*8;
    const int acb = (L >> 4)*16;
    const int axor = (alf & 7) << 4;
    const uint32_t arow0 = (uint32_t)(wm + alf)*128;
    const uint32_t arow1 = (uint32_t)(wm + 16 + alf)*128;
    const int blf = (L & 7) + (L >> 4)*8;
    const int bcb = ((L >> 3) & 1)*16;
    const int bxor = (blf & 7) << 4;
    const uint32_t brow0 = (uint32_t)(wn + blf)*128;
    const uint32_t brow1 = (uint32_t)(wn + 16 + blf)*128;

    float acc[2][4][4];
    #pragma unroll
    for (int i = 0; i < 2; i++)
        #pragma unroll
        for (int j = 0; j < 4; j++)
            #pragma unroll
            for (int c2 = 0; c2 < 4; c2++) acc[i][j][c2] = 0.0f;

    // prologue: tile t0 -> stage 0
    {
        uint32_t st = sb;
        #pragma unroll
        for (int r = 0; r < 4; r++){
            CP16(st +         s_o[r], gah[r]);
            CP16(st + 16384 + s_o[r], gal[r]);
            if (r < 2){
                CP16(st + 32768 + s_o[r], gbh[r]);
                CP16(st + 40960 + s_o[r], gbl[r]);
            }
        }
        CP_COMMIT();
    }

    for (int t = 0; t < KT; t++){
        CP_WAIT0();
        __syncthreads();

        if (t + 1 < KT){
            uint32_t st = sb + ((t+1) & 1)*STG_SZ;
            size_t kb = (size_t)(t+1)*64;
            #pragma unroll
            for (int r = 0; r < 4; r++){
                CP16(st +         s_o[r], gah[r] + kb);
                CP16(st + 16384 + s_o[r], gal[r] + kb);
                if (r < 2){
                    CP16(st + 32768 + s_o[r], gbh[r] + kb);
                    CP16(st + 40960 + s_o[r], gbl[r] + kb);
                }
            }
            CP_COMMIT();
        }

        const uint32_t st = sb + (t & 1)*STG_SZ;
        #pragma unroll
        for (int ks = 0; ks < 4; ks++){
            const uint32_t ca = (uint32_t)((ks*32 + acb) ^ axor);
            const uint32_t cb = (uint32_t)((ks*32 + bcb) ^ bxor);
            uint32_t ah[8], al[8], bh[8], bl[8];
            LDSM4(ah[0],ah[1],ah[2],ah[3], st + arow0 + ca);
            LDSM4(ah[4],ah[5],ah[6],ah[7], st + arow1 + ca);
            LDSM4(al[0],al[1],al[2],al[3], st + 16384 + arow0 + ca);
            LDSM4(al[4],al[5],al[6],al[7], st + 16384 + arow1 + ca);
            LDSM4(bh[0],bh[1],bh[2],bh[3], st + 32768 + brow0 + cb);
            LDSM4(bh[4],bh[5],bh[6],bh[7], st + 32768 + brow1 + cb);
            LDSM4(bl[0],bl[1],bl[2],bl[3], st + 40960 + brow0 + cb);
            LDSM4(bl[4],bl[5],bl[6],bl[7], st + 40960 + brow1 + cb);

            #pragma unroll
            for (int i = 0; i < 2; i++){
                #pragma unroll
                for (int j = 0; j < 4; j++){
                    MMA16816(acc[i][j], ah[i*4],ah[i*4+1],ah[i*4+2],ah[i*4+3], bh[j*2],bh[j*2+1]);
                }
            }
            #pragma unroll
            for (int i = 0; i < 2; i++){
                #pragma unroll
                for (int j = 0; j < 4; j++){
                    MMA16816(acc[i][j], al[i*4],al[i*4+1],al[i*4+2],al[i*4+3], bh[j*2],bh[j*2+1]);
                }
            }
            #pragma unroll
            for (int i = 0; i < 2; i++){
                #pragma unroll
                for (int j = 0; j < 4; j++){
                    MMA16816(acc[i][j], ah[i*4],ah[i*4+1],ah[i*4+2],ah[i*4+3], bl[j*2],bl[j*2+1]);
                }
            }
        }
    }

    const int g = L >> 2, tg = L & 3;
    #pragma unroll
    for (int i = 0; i < 2; i++){
        #pragma unroll
        for (int j = 0; j < 4; j++){
            int row = m0 + wm + i*16 + g;
            int col = n0 + wn + j*8 + 2*tg;
            float2 v0, v1;
            v0.x = acc[i][j][0]; v0.y = acc[i][j][1];
            v1.x = acc[i][j][2]; v1.y = acc[i][j][3];
            *(float2*)(part + (size_t)row*NOUT + col) = v0;
            *(float2*)(part + (size_t)(row+8)*NOUT + col) = v1;
        }
    }
}

extern "C" void kernel_launch(void* const* d_in, const int* in_sizes, int n_in,
                              void* d_out, int out_size)
{
    const float* z   = (const float*)d_in[0];
    const float* c   = (const float*)d_in[1];
    const float* w0  = (const float*)d_in[2];
    const float* b0  = (const float*)d_in[3];
    const float* w1  = (const float*)d_in[4];
    const float* b1  = (const float*)d_in[5];
    const float* w2  = (const float*)d_in[6];
    const float* b2  = (const float*)d_in[7];
    const float* gw1 = (const float*)d_in[8];
    const float* gb1 = (const float*)d_in[9];
    const float* gw2 = (const float*)d_in[10];
    const float* gb2 = (const float*)d_in[11];
    const float* gw3 = (const float*)d_in[12];
    const float* gb3 = (const float*)d_in[13];
    float* out = (float*)d_out;

    float *p0, *p1, *p2, *p3;
    __nv_bfloat16 *Ahi, *Alo, *W0hi, *W0lo, *W1hi, *W1lo, *W2hi, *W2lo;
    cudaGetSymbolAddress((void**)&p0, g_p0);
    cudaGetSymbolAddress((void**)&p1, g_p1);
    cudaGetSymbolAddress((void**)&p2, g_p2);
    cudaGetSymbolAddress((void**)&p3, g_p3);
    cudaGetSymbolAddress((void**)&Ahi, g_Ahi);
    cudaGetSymbolAddress((void**)&Alo, g_Alo);
    cudaGetSymbolAddress((void**)&W0hi, g_W0hi);
    cudaGetSymbolAddress((void**)&W0lo, g_W0lo);
    cudaGetSymbolAddress((void**)&W1hi, g_W1hi);
    cudaGetSymbolAddress((void**)&W1lo, g_W1lo);
    cudaGetSymbolAddress((void**)&W2hi, g_W2hi);
    cudaGetSymbolAddress((void**)&W2lo, g_W2lo);

    cudaFuncSetAttribute(gemm_kernel<K0P/64>, cudaFuncAttributeMaxDynamicSharedMemorySize, GSMEM);
    cudaFuncSetAttribute(gemm_kernel<K1P/64>, cudaFuncAttributeMaxDynamicSharedMemorySize, GSMEM);

    dim3 gg(8, 8, 4);   // 256 CTAs, split-K=4, 2/SM single wave

    pre_kernel<<<dim3(K1P/32, 16, 4), dim3(32, 8)>>>(w0, b0, w1, b1, w2, b2,
                                                     z, c, gw1, gb1, gw2, gb2, gw3, gb3);
    gemm_kernel<K0P/64><<<gg, 256, GSMEM>>>(Ahi, Alo, W0hi, W0lo, p0, p1, p2, p3);

    prep_combine_kernel<<<B_SZ, 256>>>(z, p0, p1, p2, p3, Ahi, Alo);
    gemm_kernel<K1P/64><<<gg, 256, GSMEM>>>(Ahi, Alo, W1hi, W1lo, p0, p1, p2, p3);

    prep_combine_kernel<<<B_SZ, 256>>>(z, p0, p1, p2, p3, Ahi, Alo);
    gemm_kernel<K1P/64><<<gg, 256, GSMEM>>>(Ahi, Alo, W2hi, W2lo, p0, p1, p2, p3);

    combine_kernel<<<B_SZ*NOUT/1024, 256>>>(p0, p1, p2, p3, out);
}

// round 9
// speedup vs baseline: 1.2449x; 1.2449x over previous
#include <cuda_runtime.h>
#include <cuda_bf16.h>
#include <math.h>
#include <stdint.h>

#define B_SZ 1024
#define LATD 64
#define FCON 256
#define IN0  320
#define HIDD 512
#define INTER 576
#define NOUT 512
#define NE   8
#define GH   64
#define K0P  2624   // 8*320+64 (bias tail)
#define K1P  4672   // 8*576+64

__device__ float g_coeff[B_SZ*NE];
__device__ float g_p0[B_SZ*NOUT];
__device__ float g_p1[B_SZ*NOUT];
__device__ float g_p2[B_SZ*NOUT];
__device__ float g_p3[B_SZ*NOUT];
__device__ __nv_bfloat16 g_Ahi[B_SZ*K1P];
__device__ __nv_bfloat16 g_Alo[B_SZ*K1P];
__device__ __nv_bfloat16 g_W0hi[NOUT*K0P];
__device__ __nv_bfloat16 g_W0lo[NOUT*K0P];
__device__ __nv_bfloat16 g_W1hi[NOUT*K1P];
__device__ __nv_bfloat16 g_W1lo[NOUT*K1P];
__device__ __nv_bfloat16 g_W2hi[NOUT*K1P];
__device__ __nv_bfloat16 g_W2lo[NOUT*K1P];

__device__ __forceinline__ float elu_f(float x){ return x > 0.0f ? x : expm1f(x); }

__device__ __forceinline__ uint32_t smem_u32(const void* p){
    uint32_t a;
    asm("{ .reg .u64 t; cvta.to.shared.u64 t, %1; cvt.u32.u64 %0, t; }" : "=r"(a) : "l"(p));
    return a;
}

#define CP16(s, g) asm volatile("cp.async.cg.shared.global [%0], [%1], 16;" :: "r"(s), "l"(g))
#define CP_COMMIT() asm volatile("cp.async.commit_group;" ::: "memory")
#define CP_WAIT0()  asm volatile("cp.async.wait_group 0;" ::: "memory")

#define LDSM4(r0,r1,r2,r3,addr) \
    asm volatile("ldmatrix.sync.aligned.m8n8.x4.shared.b16 {%0,%1,%2,%3}, [%4];" \
        : "=r"(r0), "=r"(r1), "=r"(r2), "=r"(r3) : "r"(addr))

#define MMA16816(c, a0,a1,a2,a3, b0,b1) \
    asm volatile("mma.sync.aligned.m16n8k16.row.col.f32.bf16.bf16.f32 " \
        "{%0,%1,%2,%3}, {%4,%5,%6,%7}, {%8,%9}, {%0,%1,%2,%3};" \
        : "+f"((c)[0]), "+f"((c)[1]), "+f"((c)[2]), "+f"((c)[3]) \
        : "r"(a0), "r"(a1), "r"(a2), "r"(a3), "r"(b0), "r"(b1))

__device__ __forceinline__ void split_pair(float a, float b, uint32_t& h, uint32_t& l){
    __nv_bfloat16 ha = __float2bfloat16_rn(a), hb = __float2bfloat16_rn(b);
    __nv_bfloat16 la = __float2bfloat16_rn(a - __bfloat162float(ha));
    __nv_bfloat16 lb = __float2bfloat16_rn(b - __bfloat162float(hb));
    __nv_bfloat162 H = __halves2bfloat162(ha, hb), L = __halves2bfloat162(la, lb);
    h = *reinterpret_cast<uint32_t*>(&H); l = *reinterpret_cast<uint32_t*>(&L);
}

// ---------------- fused transpose + bias-tail for all 3 layers (R7 version) ----------------
__global__ void transpose_all(
    const float* __restrict__ w0, const float* __restrict__ b0,
    const float* __restrict__ w1, const float* __restrict__ b1,
    const float* __restrict__ w2, const float* __restrict__ b2)
{
    const float *W, *bias; __nv_bfloat16 *Whi, *Wlo; int KTOT, KP;
    if (blockIdx.z == 0){ W=w0; bias=b0; Whi=g_W0hi; Wlo=g_W0lo; KTOT=NE*IN0;   KP=K0P; }
    else if (blockIdx.z == 1){ W=w1; bias=b1; Whi=g_W1hi; Wlo=g_W1lo; KTOT=NE*INTER; KP=K1P; }
    else { W=w2; bias=b2; Whi=g_W2hi; Wlo=g_W2lo; KTOT=NE*INTER; KP=K1P; }

    int k0 = blockIdx.x*32;
    if (k0 >= KP) return;
    int n0 = blockIdx.y*32;
    int x = threadIdx.x, y = threadIdx.y;   // (32, 8)

    if (k0 < KTOT){
        __shared__ float tile[32][33];
        #pragma unroll
        for (int j = 0; j < 32; j += 8)
            tile[y+j][x] = W[(size_t)(k0+y+j)*NOUT + n0 + x];
        __syncthreads();
        #pragma unroll
        for (int j = 0; j < 32; j += 8){
            float v = tile[x][y+j];
            int n = n0+y+j, k = k0+x;
            __nv_bfloat16 h = __float2bfloat16_rn(v);
            __nv_bfloat16 l = __float2bfloat16_rn(v - __bfloat162float(h));
            Whi[(size_t)n*KP + k] = h; Wlo[(size_t)n*KP + k] = l;
        }
    } else {
        int k = k0 + x, j = k - KTOT;
        #pragma unroll
        for (int r = 0; r < 32; r += 8){
            int n = n0 + y + r;
            float v = (j < NE) ? bias[j*NOUT + n] : 0.0f;
            __nv_bfloat16 h = __float2bfloat16_rn(v);
            __nv_bfloat16 l = __float2bfloat16_rn(v - __bfloat162float(h));
            Whi[(size_t)n*KP + k] = h; Wlo[(size_t)n*KP + k] = l;
        }
    }
}

// ---------------- fused gate + layer-0 A' build (R7 version) ----------------
__global__ __launch_bounds__(256) void gate_prep_kernel(
    const float* __restrict__ z, const float* __restrict__ c,
    const float* __restrict__ gw1, const float* __restrict__ gb1,
    const float* __restrict__ gw2, const float* __restrict__ gb2,
    const float* __restrict__ gw3, const float* __restrict__ gb3,
    __nv_bfloat16* __restrict__ Ahi, __nv_bfloat16* __restrict__ Alo)
{
    __shared__ float x[IN0], h1[GH], h2[GH], lg[NE], cf[NE];
    int b = blockIdx.x, tid = threadIdx.x;

    if (tid < LATD) x[tid] = z[b*LATD + tid];
    for (int i = tid; i < FCON; i += 256) x[LATD+i] = c[b*FCON + i];
    __syncthreads();

    if (tid < GH){
        float acc = gb1[tid];
        #pragma unroll 8
        for (int i = 0; i < IN0; i++) acc += x[i]*gw1[i*GH + tid];
        h1[tid] = elu_f(acc);
    }
    __syncthreads();
    if (tid < GH){
        float acc = gb2[tid];
        #pragma unroll 8
        for (int i = 0; i < GH; i++) acc += h1[i]*gw2[i*GH + tid];
        h2[tid] = elu_f(acc);
    }
    __syncthreads();
    if (tid < NE){
        float a = gb3[tid];
        #pragma unroll 8
        for (int i = 0; i < GH; i++) a += h2[i]*gw3[i*NE + tid];
        lg[tid] = a;
    }
    __syncthreads();
    if (tid < NE){
        float m = lg[0];
        #pragma unroll
        for (int i = 1; i < NE; i++) m = fmaxf(m, lg[i]);
        float s = 0.f;
        #pragma unroll
        for (int i = 0; i < NE; i++) s += expf(lg[i]-m);
        float cv = expf(lg[tid]-m)/s;
        cf[tid] = cv;
        g_coeff[b*NE + tid] = cv;
    }
    __syncthreads();

    uint4* oh = (uint4*)(Ahi + (size_t)b*K0P);
    uint4* ol = (uint4*)(Alo + (size_t)b*K0P);
    const int inu = IN0 >> 3, main_u = NE*inu, NU = K0P >> 3;
    for (int u = tid; u < NU; u += 256){
        float v[8];
        if (u < main_u){
            int e = u/inu, i8 = (u - e*inu) << 3;
            float s = cf[e];
            #pragma unroll
            for (int l = 0; l < 8; l++) v[l] = x[i8+l]*s;
        } else {
            int j = (u - main_u) << 3;
            #pragma unroll
            for (int l = 0; l < 8; l++) v[l] = (j+l < NE) ? cf[j+l] : 0.0f;
        }
        uint4 hh, ll;
        split_pair(v[0],v[1],hh.x,ll.x); split_pair(v[2],v[3],hh.y,ll.y);
        split_pair(v[4],v[5],hh.z,ll.z); split_pair(v[6],v[7],hh.w,ll.w);
        oh[u] = hh; ol[u] = ll;
    }
}

// ------- A' build for layers 1/2: prev = elu(p0+p1+p2+p3) inline -------
__global__ __launch_bounds__(256) void prep_combine_kernel(
    const float* __restrict__ z,
    const float* __restrict__ p0, const float* __restrict__ p1,
    const float* __restrict__ p2, const float* __restrict__ p3,
    __nv_bfloat16* __restrict__ Ahi, __nv_bfloat16* __restrict__ Alo)
{
    constexpr int IN = INTER, KP = K1P;
    int b = blockIdx.x, tid = threadIdx.x;
    __shared__ float cf[NE];
    __shared__ float xp[HIDD];
    if (tid < NE) cf[tid] = g_coeff[b*NE + tid];
    {
        const float4* a4 = (const float4*)(p0 + (size_t)b*NOUT);
        const float4* b4 = (const float4*)(p1 + (size_t)b*NOUT);
        const float4* c4 = (const float4*)(p2 + (size_t)b*NOUT);
        const float4* d4 = (const float4*)(p3 + (size_t)b*NOUT);
        float4* x4 = (float4*)xp;
        for (int i = tid; i < HIDD/4; i += 256){
            float4 u = a4[i], w = b4[i], s = c4[i], t = d4[i];
            float4 r;
            r.x = elu_f(u.x + w.x + s.x + t.x); r.y = elu_f(u.y + w.y + s.y + t.y);
            r.z = elu_f(u.z + w.z + s.z + t.z); r.w = elu_f(u.w + w.w + s.w + t.w);
            x4[i] = r;
        }
    }
    __syncthreads();

    const float4* z4 = (const float4*)(z + (size_t)b*LATD);
    uint4* oh = (uint4*)(Ahi + (size_t)b*KP);
    uint4* ol = (uint4*)(Alo + (size_t)b*KP);
    const int inu = IN >> 3, main_u = NE*inu, NU = KP >> 3;
    for (int u = tid; u < NU; u += 256){
        float v[8];
        if (u < main_u){
            int e = u/inu, i8 = (u - e*inu) << 3;
            float s = cf[e];
            if (i8 < LATD){
                float4 x0 = z4[i8>>2], x1 = z4[(i8>>2)+1];
                v[0]=x0.x*s; v[1]=x0.y*s; v[2]=x0.z*s; v[3]=x0.w*s;
                v[4]=x1.x*s; v[5]=x1.y*s; v[6]=x1.z*s; v[7]=x1.w*s;
            } else {
                int q = i8 - LATD;
                #pragma unroll
                for (int l = 0; l < 8; l++) v[l] = xp[q+l]*s;
            }
        } else {
            int j = (u - main_u) << 3;
            #pragma unroll
            for (int l = 0; l < 8; l++) v[l] = (j+l < NE) ? cf[j+l] : 0.0f;
        }
        uint4 hh, ll;
        split_pair(v[0],v[1],hh.x,ll.x); split_pair(v[2],v[3],hh.y,ll.y);
        split_pair(v[4],v[5],hh.z,ll.z); split_pair(v[6],v[7],hh.w,ll.w);
        oh[u] = hh; ol[u] = ll;
    }
}

// ------- final combine: out = p0+p1+p2+p3 -------
__global__ __launch_bounds__(256) void combine_kernel(
    const float* __restrict__ p0, const float* __restrict__ p1,
    const float* __restrict__ p2, const float* __restrict__ p3, float* __restrict__ out)
{
    int i = blockIdx.x*256 + threadIdx.x;
    const float4* a4 = (const float4*)p0;
    const float4* b4 = (const float4*)p1;
    const float4* c4 = (const float4*)p2;
    const float4* d4 = (const float4*)p3;
    float4* o4 = (float4*)out;
    float4 u = a4[i], w = b4[i], s = c4[i], t = d4[i];
    float4 r;
    r.x = u.x+w.x+s.x+t.x; r.y = u.y+w.y+s.y+t.y;
    r.z = u.z+w.z+s.z+t.z; r.w = u.w+w.w+s.w+t.w;
    o4[i] = r;
}

// ------- GEMM: CTA 128x64, warp 32x32 (4m x 2n), split-K=4, 2-stage, staged passes -------
// Stage (48KB): AH@0(16K) AL@16384 BH@32768(8K) BL@40960; 2 stages = 96KB.
#define STG_SZ 49152
#define GSMEM (2*STG_SZ)

template<int KTOT>
__global__ __launch_bounds__(256, 2) void gemm_kernel(
    const __nv_bfloat16* __restrict__ Ahi, const __nv_bfloat16* __restrict__ Alo,
    const __nv_bfloat16* __restrict__ Whi, const __nv_bfloat16* __restrict__ Wlo,
    float* __restrict__ p0, float* __restrict__ p1,
    float* __restrict__ p2, float* __restrict__ p3)
{
    constexpr int KP = KTOT*64;
    constexpr int q = KTOT/4, rr = KTOT%4;
    extern __shared__ char smem[];
    const uint32_t sb = smem_u32(smem);
    const int tid = threadIdx.x, wid = tid >> 5, L = tid & 31;
    const int m0 = blockIdx.y*128, n0 = blockIdx.x*64;
    const int wm = (wid & 3)*32, wn = (wid >> 2)*32;
    const int zz = blockIdx.z;
    const int KT = q + (zz < rr ? 1 : 0);
    const int t0 = zz*q + (zz < rr ? zz : rr);
    float* part = (zz == 0) ? p0 : (zz == 1) ? p1 : (zz == 2) ? p2 : p3;

    uint32_t s_o[4];
    const __nv_bfloat16 *gah[4], *gal[4], *gbh[2], *gbl[2];
    #pragma unroll
    for (int r = 0; r < 4; r++){
        int ch = tid + r*256, row = ch >> 3, kc = ch & 7;
        s_o[r] = row*128 + ((kc*16) ^ ((row & 7) << 4));
        size_t kb0 = (size_t)t0*64 + kc*8;
        gah[r] = Ahi + (size_t)(m0+row)*KP + kb0;
        gal[r] = Alo + (size_t)(m0+row)*KP + kb0;
        if (r < 2){
            gbh[r] = Whi + (size_t)(n0+row)*KP + kb0;
            gbl[r] = Wlo + (size_t)(n0+row)*KP + kb0;
        }
    }

    const int alf = (L & 7) + ((L >> 3) & 1)*8;
    const int acb = (L >> 4)*16;
    const int axor = (alf & 7) << 4;
    const uint32_t arow0 = (uint32_t)(wm + alf)*128;
    const uint32_t arow1 = (uint32_t)(wm + 16 + alf)*128;
    const int blf = (L & 7) + (L >> 4)*8;
    const int bcb = ((L >> 3) & 1)*16;
    const int bxor = (blf & 7) << 4;
    const uint32_t brow0 = (uint32_t)(wn + blf)*128;
    const uint32_t brow1 = (uint32_t)(wn + 16 + blf)*128;

    float acc[2][4][4];
    #pragma unroll
    for (int i = 0; i < 2; i++)
        #pragma unroll
        for (int j = 0; j < 4; j++)
            #pragma unroll
            for (int c2 = 0; c2 < 4; c2++) acc[i][j][c2] = 0.0f;

    // prologue: tile t0 -> stage 0
    {
        uint32_t st = sb;
        #pragma unroll
        for (int r = 0; r < 4; r++){
            CP16(st +         s_o[r], gah[r]);
            CP16(st + 16384 + s_o[r], gal[r]);
            if (r < 2){
                CP16(st + 32768 + s_o[r], gbh[r]);
                CP16(st + 40960 + s_o[r], gbl[r]);
            }
        }
        CP_COMMIT();
    }

    for (int t = 0; t < KT; t++){
        CP_WAIT0();
        __syncthreads();

        if (t + 1 < KT){
            uint32_t st = sb + ((t+1) & 1)*STG_SZ;
            size_t kb = (size_t)(t+1)*64;
            #pragma unroll
            for (int r = 0; r < 4; r++){
                CP16(st +         s_o[r], gah[r] + kb);
                CP16(st + 16384 + s_o[r], gal[r] + kb);
                if (r < 2){
                    CP16(st + 32768 + s_o[r], gbh[r] + kb);
                    CP16(st + 40960 + s_o[r], gbl[r] + kb);
                }
            }
            CP_COMMIT();
        }

        const uint32_t st = sb + (t & 1)*STG_SZ;
        #pragma unroll
        for (int ks = 0; ks < 4; ks++){
            const uint32_t ca = (uint32_t)((ks*32 + acb) ^ axor);
            const uint32_t cb = (uint32_t)((ks*32 + bcb) ^ bxor);
            // staged passes: peak live fragment regs 24 (vs 32)
            uint32_t a0[8], b0r[8];
            LDSM4(a0[0],a0[1],a0[2],a0[3], st + arow0 + ca);
            LDSM4(a0[4],a0[5],a0[6],a0[7], st + arow1 + ca);
            LDSM4(b0r[0],b0r[1],b0r[2],b0r[3], st + 32768 + brow0 + cb);
            LDSM4(b0r[4],b0r[5],b0r[6],b0r[7], st + 32768 + brow1 + cb);
            #pragma unroll
            for (int i = 0; i < 2; i++)
                #pragma unroll
                for (int j = 0; j < 4; j++)
                    MMA16816(acc[i][j], a0[i*4],a0[i*4+1],a0[i*4+2],a0[i*4+3], b0r[j*2],b0r[j*2+1]);

            uint32_t a1[8];
            LDSM4(a1[0],a1[1],a1[2],a1[3], st + 16384 + arow0 + ca);
            LDSM4(a1[4],a1[5],a1[6],a1[7], st + 16384 + arow1 + ca);
            #pragma unroll
            for (int i = 0; i < 2; i++)
                #pragma unroll
                for (int j = 0; j < 4; j++)
                    MMA16816(acc[i][j], a1[i*4],a1[i*4+1],a1[i*4+2],a1[i*4+3], b0r[j*2],b0r[j*2+1]);

            uint32_t b1r[8];
            LDSM4(b1r[0],b1r[1],b1r[2],b1r[3], st + 40960 + brow0 + cb);
            LDSM4(b1r[4],b1r[5],b1r[6],b1r[7], st + 40960 + brow1 + cb);
            #pragma unroll
            for (int i = 0; i < 2; i++)
                #pragma unroll
                for (int j = 0; j < 4; j++)
                    MMA16816(acc[i][j], a0[i*4],a0[i*4+1],a0[i*4+2],a0[i*4+3], b1r[j*2],b1r[j*2+1]);
        }
    }

    const int g = L >> 2, tg = L & 3;
    #pragma unroll
    for (int i = 0; i < 2; i++){
        #pragma unroll
        for (int j = 0; j < 4; j++){
            int row = m0 + wm + i*16 + g;
            int col = n0 + wn + j*8 + 2*tg;
            float2 v0, v1;
            v0.x = acc[i][j][0]; v0.y = acc[i][j][1];
            v1.x = acc[i][j][2]; v1.y = acc[i][j][3];
            *(float2*)(part + (size_t)row*NOUT + col) = v0;
            *(float2*)(part + (size_t)(row+8)*NOUT + col) = v1;
        }
    }
}

extern "C" void kernel_launch(void* const* d_in, const int* in_sizes, int n_in,
                              void* d_out, int out_size)
{
    const float* z   = (const float*)d_in[0];
    const float* c   = (const float*)d_in[1];
    const float* w0  = (const float*)d_in[2];
    const float* b0  = (const float*)d_in[3];
    const float* w1  = (const float*)d_in[4];
    const float* b1  = (const float*)d_in[5];
    const float* w2  = (const float*)d_in[6];
    const float* b2  = (const float*)d_in[7];
    const float* gw1 = (const float*)d_in[8];
    const float* gb1 = (const float*)d_in[9];
    const float* gw2 = (const float*)d_in[10];
    const float* gb2 = (const float*)d_in[11];
    const float* gw3 = (const float*)d_in[12];
    const float* gb3 = (const float*)d_in[13];
    float* out = (float*)d_out;

    float *p0, *p1, *p2, *p3;
    __nv_bfloat16 *Ahi, *Alo, *W0hi, *W0lo, *W1hi, *W1lo, *W2hi, *W2lo;
    cudaGetSymbolAddress((void**)&p0, g_p0);
    cudaGetSymbolAddress((void**)&p1, g_p1);
    cudaGetSymbolAddress((void**)&p2, g_p2);
    cudaGetSymbolAddress((void**)&p3, g_p3);
    cudaGetSymbolAddress((void**)&Ahi, g_Ahi);
    cudaGetSymbolAddress((void**)&Alo, g_Alo);
    cudaGetSymbolAddress((void**)&W0hi, g_W0hi);
    cudaGetSymbolAddress((void**)&W0lo, g_W0lo);
    cudaGetSymbolAddress((void**)&W1hi, g_W1hi);
    cudaGetSymbolAddress((void**)&W1lo, g_W1lo);
    cudaGetSymbolAddress((void**)&W2hi, g_W2hi);
    cudaGetSymbolAddress((void**)&W2lo, g_W2lo);

    cudaFuncSetAttribute(gemm_kernel<K0P/64>, cudaFuncAttributeMaxDynamicSharedMemorySize, GSMEM);
    cudaFuncSetAttribute(gemm_kernel<K1P/64>, cudaFuncAttributeMaxDynamicSharedMemorySize, GSMEM);

    dim3 gg(8, 8, 4);   // 256 CTAs, split-K=4, 2/SM single wave

    transpose_all<<<dim3(K1P/32, 16, 3), dim3(32, 8)>>>(w0, b0, w1, b1, w2, b2);
    gate_prep_kernel<<<B_SZ, 256>>>(z, c, gw1, gb1, gw2, gb2, gw3, gb3, Ahi, Alo);
    gemm_kernel<K0P/64><<<gg, 256, GSMEM>>>(Ahi, Alo, W0hi, W0lo, p0, p1, p2, p3);

    prep_combine_kernel<<<B_SZ, 256>>>(z, p0, p1, p2, p3, Ahi, Alo);
    gemm_kernel<K1P/64><<<gg, 256, GSMEM>>>(Ahi, Alo, W1hi, W1lo, p0, p1, p2, p3);

    prep_combine_kernel<<<B_SZ, 256>>>(z, p0, p1, p2, p3, Ahi, Alo);
    gemm_kernel<K1P/64><<<gg, 256, GSMEM>>>(Ahi, Alo, W2hi, W2lo, p0, p1, p2, p3);

    combine_kernel<<<B_SZ*NOUT/1024, 256>>>(p0, p1, p2, p3, out);
}

// round 10
// speedup vs baseline: 1.3024x; 1.0462x over previous
#include <cuda_runtime.h>
#include <cuda_bf16.h>
#include <math.h>
#include <stdint.h>

#define B_SZ 1024
#define LATD 64
#define FCON 256
#define IN0  320
#define HIDD 512
#define INTER 576
#define NOUT 512
#define NE   8
#define GH   64
#define K0P  2624   // 8*320+64 (bias tail)
#define K1P  4672   // 8*576+64

__device__ float g_coeff[B_SZ*NE];
__device__ float g_p0[B_SZ*NOUT];
__device__ float g_p1[B_SZ*NOUT];
__device__ float g_p2[B_SZ*NOUT];
__device__ float g_p3[B_SZ*NOUT];
__device__ __nv_bfloat16 g_Ahi[B_SZ*K1P];
__device__ __nv_bfloat16 g_Alo[B_SZ*K1P];
// W buffers now [KP rows][512 cols] (k-major rows)
__device__ __nv_bfloat16 g_W0hi[K0P*NOUT];
__device__ __nv_bfloat16 g_W0lo[K0P*NOUT];
__device__ __nv_bfloat16 g_W1hi[K1P*NOUT];
__device__ __nv_bfloat16 g_W1lo[K1P*NOUT];
__device__ __nv_bfloat16 g_W2hi[K1P*NOUT];
__device__ __nv_bfloat16 g_W2lo[K1P*NOUT];

__device__ __forceinline__ float elu_f(float x){ return x > 0.0f ? x : expm1f(x); }

__device__ __forceinline__ uint32_t smem_u32(const void* p){
    uint32_t a;
    asm("{ .reg .u64 t; cvta.to.shared.u64 t, %1; cvt.u32.u64 %0, t; }" : "=r"(a) : "l"(p));
    return a;
}

#define CP16(s, g) asm volatile("cp.async.cg.shared.global [%0], [%1], 16;" :: "r"(s), "l"(g))
#define CP_COMMIT() asm volatile("cp.async.commit_group;" ::: "memory")
#define CP_WAIT0()  asm volatile("cp.async.wait_group 0;" ::: "memory")

#define LDSM4(r0,r1,r2,r3,addr) \
    asm volatile("ldmatrix.sync.aligned.m8n8.x4.shared.b16 {%0,%1,%2,%3}, [%4];" \
        : "=r"(r0), "=r"(r1), "=r"(r2), "=r"(r3) : "r"(addr))

#define LDSM4T(r0,r1,r2,r3,addr) \
    asm volatile("ldmatrix.sync.aligned.m8n8.x4.trans.shared.b16 {%0,%1,%2,%3}, [%4];" \
        : "=r"(r0), "=r"(r1), "=r"(r2), "=r"(r3) : "r"(addr))

#define MMA16816(c, a0,a1,a2,a3, b0,b1) \
    asm volatile("mma.sync.aligned.m16n8k16.row.col.f32.bf16.bf16.f32 " \
        "{%0,%1,%2,%3}, {%4,%5,%6,%7}, {%8,%9}, {%0,%1,%2,%3};" \
        : "+f"((c)[0]), "+f"((c)[1]), "+f"((c)[2]), "+f"((c)[3]) \
        : "r"(a0), "r"(a1), "r"(a2), "r"(a3), "r"(b0), "r"(b1))

__device__ __forceinline__ void split_pair(float a, float b, uint32_t& h, uint32_t& l){
    __nv_bfloat16 ha = __float2bfloat16_rn(a), hb = __float2bfloat16_rn(b);
    __nv_bfloat16 la = __float2bfloat16_rn(a - __bfloat162float(ha));
    __nv_bfloat16 lb = __float2bfloat16_rn(b - __bfloat162float(hb));
    __nv_bfloat162 H = __halves2bfloat162(ha, hb), L = __halves2bfloat162(la, lb);
    h = *reinterpret_cast<uint32_t*>(&H); l = *reinterpret_cast<uint32_t*>(&L);
}

// ------- streaming W convert (no transpose): fp32 [K,512] -> bf16 hi/lo [KP,512] + bias tail -------
__global__ __launch_bounds__(256) void convert_w(
    const float* __restrict__ w0, const float* __restrict__ b0,
    const float* __restrict__ w1, const float* __restrict__ b1,
    const float* __restrict__ w2, const float* __restrict__ b2)
{
    const float *W, *bias; __nv_bfloat16 *Whi, *Wlo; int KTOT, KP;
    if (blockIdx.z == 0){ W=w0; bias=b0; Whi=g_W0hi; Wlo=g_W0lo; KTOT=NE*IN0;   KP=K0P; }
    else if (blockIdx.z == 1){ W=w1; bias=b1; Whi=g_W1hi; Wlo=g_W1lo; KTOT=NE*INTER; KP=K1P; }
    else { W=w2; bias=b2; Whi=g_W2hi; Wlo=g_W2lo; KTOT=NE*INTER; KP=K1P; }

    size_t lin = (size_t)blockIdx.x*2048 + (size_t)threadIdx.x*8;
    int k = (int)(lin >> 9);
    if (k >= KP) return;
    int n = (int)(lin & 511);

    float v[8];
    if (k < KTOT){
        const float4* src = (const float4*)(W + (size_t)k*NOUT + n);
        float4 x0 = src[0], x1 = src[1];
        v[0]=x0.x; v[1]=x0.y; v[2]=x0.z; v[3]=x0.w;
        v[4]=x1.x; v[5]=x1.y; v[6]=x1.z; v[7]=x1.w;
    } else {
        int j = k - KTOT;
        if (j < NE){
            const float4* src = (const float4*)(bias + (size_t)j*NOUT + n);
            float4 x0 = src[0], x1 = src[1];
            v[0]=x0.x; v[1]=x0.y; v[2]=x0.z; v[3]=x0.w;
            v[4]=x1.x; v[5]=x1.y; v[6]=x1.z; v[7]=x1.w;
        } else {
            #pragma unroll
            for (int l = 0; l < 8; l++) v[l] = 0.0f;
        }
    }
    uint4 hh, ll;
    split_pair(v[0],v[1],hh.x,ll.x); split_pair(v[2],v[3],hh.y,ll.y);
    split_pair(v[4],v[5],hh.z,ll.z); split_pair(v[6],v[7],hh.w,ll.w);
    *(uint4*)(Whi + (size_t)k*NOUT + n) = hh;
    *(uint4*)(Wlo + (size_t)k*NOUT + n) = ll;
}

// ---------------- fused gate + layer-0 A' build ----------------
__global__ __launch_bounds__(256) void gate_prep_kernel(
    const float* __restrict__ z, const float* __restrict__ c,
    const float* __restrict__ gw1, const float* __restrict__ gb1,
    const float* __restrict__ gw2, const float* __restrict__ gb2,
    const float* __restrict__ gw3, const float* __restrict__ gb3,
    __nv_bfloat16* __restrict__ Ahi, __nv_bfloat16* __restrict__ Alo)
{
    __shared__ float x[IN0], h1[GH], h2[GH], lg[NE], cf[NE];
    int b = blockIdx.x, tid = threadIdx.x;

    if (tid < LATD) x[tid] = z[b*LATD + tid];
    for (int i = tid; i < FCON; i += 256) x[LATD+i] = c[b*FCON + i];
    __syncthreads();

    if (tid < GH){
        float acc = gb1[tid];
        #pragma unroll 8
        for (int i = 0; i < IN0; i++) acc += x[i]*gw1[i*GH + tid];
        h1[tid] = elu_f(acc);
    }
    __syncthreads();
    if (tid < GH){
        float acc = gb2[tid];
        #pragma unroll 8
        for (int i = 0; i < GH; i++) acc += h1[i]*gw2[i*GH + tid];
        h2[tid] = elu_f(acc);
    }
    __syncthreads();
    if (tid < NE){
        float a = gb3[tid];
        #pragma unroll 8
        for (int i = 0; i < GH; i++) a += h2[i]*gw3[i*NE + tid];
        lg[tid] = a;
    }
    __syncthreads();
    if (tid < NE){
        float m = lg[0];
        #pragma unroll
        for (int i = 1; i < NE; i++) m = fmaxf(m, lg[i]);
        float s = 0.f;
        #pragma unroll
        for (int i = 0; i < NE; i++) s += expf(lg[i]-m);
        float cv = expf(lg[tid]-m)/s;
        cf[tid] = cv;
        g_coeff[b*NE + tid] = cv;
    }
    __syncthreads();

    uint4* oh = (uint4*)(Ahi + (size_t)b*K0P);
    uint4* ol = (uint4*)(Alo + (size_t)b*K0P);
    const int inu = IN0 >> 3, main_u = NE*inu, NU = K0P >> 3;
    for (int u = tid; u < NU; u += 256){
        float v[8];
        if (u < main_u){
            int e = u/inu, i8 = (u - e*inu) << 3;
            float s = cf[e];
            #pragma unroll
            for (int l = 0; l < 8; l++) v[l] = x[i8+l]*s;
        } else {
            int j = (u - main_u) << 3;
            #pragma unroll
            for (int l = 0; l < 8; l++) v[l] = (j+l < NE) ? cf[j+l] : 0.0f;
        }
        uint4 hh, ll;
        split_pair(v[0],v[1],hh.x,ll.x); split_pair(v[2],v[3],hh.y,ll.y);
        split_pair(v[4],v[5],hh.z,ll.z); split_pair(v[6],v[7],hh.w,ll.w);
        oh[u] = hh; ol[u] = ll;
    }
}

// ------- A' build for layers 1/2: prev = elu(p0+p1+p2+p3) inline -------
__global__ __launch_bounds__(256) void prep_combine_kernel(
    const float* __restrict__ z,
    const float* __restrict__ p0, const float* __restrict__ p1,
    const float* __restrict__ p2, const float* __restrict__ p3,
    __nv_bfloat16* __restrict__ Ahi, __nv_bfloat16* __restrict__ Alo)
{
    constexpr int IN = INTER, KP = K1P;
    int b = blockIdx.x, tid = threadIdx.x;
    __shared__ float cf[NE];
    __shared__ float xp[HIDD];
    if (tid < NE) cf[tid] = g_coeff[b*NE + tid];
    {
        const float4* a4 = (const float4*)(p0 + (size_t)b*NOUT);
        const float4* b4 = (const float4*)(p1 + (size_t)b*NOUT);
        const float4* c4 = (const float4*)(p2 + (size_t)b*NOUT);
        const float4* d4 = (const float4*)(p3 + (size_t)b*NOUT);
        float4* x4 = (float4*)xp;
        for (int i = tid; i < HIDD/4; i += 256){
            float4 u = a4[i], w = b4[i], s = c4[i], t = d4[i];
            float4 r;
            r.x = elu_f(u.x + w.x + s.x + t.x); r.y = elu_f(u.y + w.y + s.y + t.y);
            r.z = elu_f(u.z + w.z + s.z + t.z); r.w = elu_f(u.w + w.w + s.w + t.w);
            x4[i] = r;
        }
    }
    __syncthreads();

    const float4* z4 = (const float4*)(z + (size_t)b*LATD);
    uint4* oh = (uint4*)(Ahi + (size_t)b*KP);
    uint4* ol = (uint4*)(Alo + (size_t)b*KP);
    const int inu = IN >> 3, main_u = NE*inu, NU = KP >> 3;
    for (int u = tid; u < NU; u += 256){
        float v[8];
        if (u < main_u){
            int e = u/inu, i8 = (u - e*inu) << 3;
            float s = cf[e];
            if (i8 < LATD){
                float4 x0 = z4[i8>>2], x1 = z4[(i8>>2)+1];
                v[0]=x0.x*s; v[1]=x0.y*s; v[2]=x0.z*s; v[3]=x0.w*s;
                v[4]=x1.x*s; v[5]=x1.y*s; v[6]=x1.z*s; v[7]=x1.w*s;
            } else {
                int q = i8 - LATD;
                #pragma unroll
                for (int l = 0; l < 8; l++) v[l] = xp[q+l]*s;
            }
        } else {
            int j = (u - main_u) << 3;
            #pragma unroll
            for (int l = 0; l < 8; l++) v[l] = (j+l < NE) ? cf[j+l] : 0.0f;
        }
        uint4 hh, ll;
        split_pair(v[0],v[1],hh.x,ll.x); split_pair(v[2],v[3],hh.y,ll.y);
        split_pair(v[4],v[5],hh.z,ll.z); split_pair(v[6],v[7],hh.w,ll.w);
        oh[u] = hh; ol[u] = ll;
    }
}

// ------- final combine: out = p0+p1+p2+p3 -------
__global__ __launch_bounds__(256) void combine_kernel(
    const float* __restrict__ p0, const float* __restrict__ p1,
    const float* __restrict__ p2, const float* __restrict__ p3, float* __restrict__ out)
{
    int i = blockIdx.x*256 + threadIdx.x;
    const float4* a4 = (const float4*)p0;
    const float4* b4 = (const float4*)p1;
    const float4* c4 = (const float4*)p2;
    const float4* d4 = (const float4*)p3;
    float4* o4 = (float4*)out;
    float4 u = a4[i], w = b4[i], s = c4[i], t = d4[i];
    float4 r;
    r.x = u.x+w.x+s.x+t.x; r.y = u.y+w.y+s.y+t.y;
    r.z = u.z+w.z+s.z+t.z; r.w = u.w+w.w+s.w+t.w;
    o4[i] = r;
}

// ------- GEMM: CTA 128x64, warp 32x32 (4m x 2n), split-K=4, 2-stage, staged passes -------
// B now [k][n] in gmem and smem; B fragments via ldmatrix.trans.
// Stage (48KB): AH@0(16K) AL@16384 BH@32768(8K) BL@40960; 2 stages = 96KB.
#define STG_SZ 49152
#define GSMEM (2*STG_SZ)

template<int KTOT>
__global__ __launch_bounds__(256, 2) void gemm_kernel(
    const __nv_bfloat16* __restrict__ Ahi, const __nv_bfloat16* __restrict__ Alo,
    const __nv_bfloat16* __restrict__ Whi, const __nv_bfloat16* __restrict__ Wlo,
    float* __restrict__ p0, float* __restrict__ p1,
    float* __restrict__ p2, float* __restrict__ p3)
{
    constexpr int KP = KTOT*64;
    constexpr int q = KTOT/4, rr = KTOT%4;
    extern __shared__ char smem[];
    const uint32_t sb = smem_u32(smem);
    const int tid = threadIdx.x, wid = tid >> 5, L = tid & 31;
    const int m0 = blockIdx.y*128, n0 = blockIdx.x*64;
    const int wm = (wid & 3)*32, wn = (wid >> 2)*32;
    const int zz = blockIdx.z;
    const int KT = q + (zz < rr ? 1 : 0);
    const int t0 = zz*q + (zz < rr ? zz : rr);
    float* part = (zz == 0) ? p0 : (zz == 1) ? p1 : (zz == 2) ? p2 : p3;

    uint32_t s_o[4];
    const __nv_bfloat16 *gah[4], *gal[4], *gbh[2], *gbl[2];
    #pragma unroll
    for (int r = 0; r < 4; r++){
        int ch = tid + r*256, row = ch >> 3, kc = ch & 7;
        s_o[r] = row*128 + ((kc*16) ^ ((row & 7) << 4));
        size_t kb0 = (size_t)t0*64 + kc*8;
        gah[r] = Ahi + (size_t)(m0+row)*KP + kb0;
        gal[r] = Alo + (size_t)(m0+row)*KP + kb0;
        if (r < 2){
            // B tile: row = k-row within tile, chunk kc -> n offset kc*8
            gbh[r] = Whi + (size_t)(t0*64 + row)*NOUT + n0 + kc*8;
            gbl[r] = Wlo + (size_t)(t0*64 + row)*NOUT + n0 + kc*8;
        }
    }

    // A fragment addressing (unchanged)
    const int alf = (L & 7) + ((L >> 3) & 1)*8;
    const int acb = (L >> 4)*16;
    const int axor = (alf & 7) << 4;
    const uint32_t arow0 = (uint32_t)(wm + alf)*128;
    const uint32_t arow1 = (uint32_t)(wm + 16 + alf)*128;
    // B fragment addressing (ldmatrix.trans on [k][n] tiles)
    const int mm = L >> 3, lr = L & 7;
    const uint32_t bconst = (uint32_t)(((mm & 1)*8 + lr)*128);
    const uint32_t bxor2 = (uint32_t)(lr << 4);
    const uint32_t bn0 = (uint32_t)((wn + (mm >> 1)*8)*2);

    float acc[2][4][4];
    #pragma unroll
    for (int i = 0; i < 2; i++)
        #pragma unroll
        for (int j = 0; j < 4; j++)
            #pragma unroll
            for (int c2 = 0; c2 < 4; c2++) acc[i][j][c2] = 0.0f;

    // prologue: tile t0 -> stage 0
    {
        uint32_t st = sb;
        #pragma unroll
        for (int r = 0; r < 4; r++){
            CP16(st +         s_o[r], gah[r]);
            CP16(st + 16384 + s_o[r], gal[r]);
            if (r < 2){
                CP16(st + 32768 + s_o[r], gbh[r]);
                CP16(st + 40960 + s_o[r], gbl[r]);
            }
        }
        CP_COMMIT();
    }

    for (int t = 0; t < KT; t++){
        CP_WAIT0();
        __syncthreads();

        if (t + 1 < KT){
            uint32_t st = sb + ((t+1) & 1)*STG_SZ;
            size_t kbA = (size_t)(t+1)*64;          // A: +64 elems along K
            size_t kbB = (size_t)(t+1)*64*NOUT;     // B: +64 rows
            #pragma unroll
            for (int r = 0; r < 4; r++){
                CP16(st +         s_o[r], gah[r] + kbA);
                CP16(st + 16384 + s_o[r], gal[r] + kbA);
                if (r < 2){
                    CP16(st + 32768 + s_o[r], gbh[r] + kbB);
                    CP16(st + 40960 + s_o[r], gbl[r] + kbB);
                }
            }
            CP_COMMIT();
        }

        const uint32_t st = sb + (t & 1)*STG_SZ;
        #pragma unroll
        for (int ks = 0; ks < 4; ks++){
            const uint32_t ca = (uint32_t)((ks*32 + acb) ^ axor);
            const uint32_t bk = (uint32_t)(ks*2048) + bconst;
            // staged passes: peak live fragment regs 24
            uint32_t a0[8], b0r[8];
            LDSM4(a0[0],a0[1],a0[2],a0[3], st + arow0 + ca);
            LDSM4(a0[4],a0[5],a0[6],a0[7], st + arow1 + ca);
            LDSM4T(b0r[0],b0r[1],b0r[2],b0r[3], st + 32768 + bk + (bn0 ^ bxor2));
            LDSM4T(b0r[4],b0r[5],b0r[6],b0r[7], st + 32768 + bk + ((bn0 + 32) ^ bxor2));
            #pragma unroll
            for (int i = 0; i < 2; i++)
                #pragma unroll
                for (int j = 0; j < 4; j++)
                    MMA16816(acc[i][j], a0[i*4],a0[i*4+1],a0[i*4+2],a0[i*4+3], b0r[j*2],b0r[j*2+1]);

            uint32_t a1[8];
            LDSM4(a1[0],a1[1],a1[2],a1[3], st + 16384 + arow0 + ca);
            LDSM4(a1[4],a1[5],a1[6],a1[7], st + 16384 + arow1 + ca);
            #pragma unroll
            for (int i = 0; i < 2; i++)
                #pragma unroll
                for (int j = 0; j < 4; j++)
                    MMA16816(acc[i][j], a1[i*4],a1[i*4+1],a1[i*4+2],a1[i*4+3], b0r[j*2],b0r[j*2+1]);

            uint32_t b1r[8];
            LDSM4T(b1r[0],b1r[1],b1r[2],b1r[3], st + 40960 + bk + (bn0 ^ bxor2));
            LDSM4T(b1r[4],b1r[5],b1r[6],b1r[7], st + 40960 + bk + ((bn0 + 32) ^ bxor2));
            #pragma unroll
            for (int i = 0; i < 2; i++)
                #pragma unroll
                for (int j = 0; j < 4; j++)
                    MMA16816(acc[i][j], a0[i*4],a0[i*4+1],a0[i*4+2],a0[i*4+3], b1r[j*2],b1r[j*2+1]);
        }
    }

    const int g = L >> 2, tg = L & 3;
    #pragma unroll
    for (int i = 0; i < 2; i++){
        #pragma unroll
        for (int j = 0; j < 4; j++){
            int row = m0 + wm + i*16 + g;
            int col = n0 + wn + j*8 + 2*tg;
            float2 v0, v1;
            v0.x = acc[i][j][0]; v0.y = acc[i][j][1];
            v1.x = acc[i][j][2]; v1.y = acc[i][j][3];
            *(float2*)(part + (size_t)row*NOUT + col) = v0;
            *(float2*)(part + (size_t)(row+8)*NOUT + col) = v1;
        }
    }
}

extern "C" void kernel_launch(void* const* d_in, const int* in_sizes, int n_in,
                              void* d_out, int out_size)
{
    const float* z   = (const float*)d_in[0];
    const float* c   = (const float*)d_in[1];
    const float* w0  = (const float*)d_in[2];
    const float* b0  = (const float*)d_in[3];
    const float* w1  = (const float*)d_in[4];
    const float* b1  = (const float*)d_in[5];
    const float* w2  = (const float*)d_in[6];
    const float* b2  = (const float*)d_in[7];
    const float* gw1 = (const float*)d_in[8];
    const float* gb1 = (const float*)d_in[9];
    const float* gw2 = (const float*)d_in[10];
    const float* gb2 = (const float*)d_in[11];
    const float* gw3 = (const float*)d_in[12];
    const float* gb3 = (const float*)d_in[13];
    float* out = (float*)d_out;

    float *p0, *p1, *p2, *p3;
    __nv_bfloat16 *Ahi, *Alo, *W0hi, *W0lo, *W1hi, *W1lo, *W2hi, *W2lo;
    cudaGetSymbolAddress((void**)&p0, g_p0);
    cudaGetSymbolAddress((void**)&p1, g_p1);
    cudaGetSymbolAddress((void**)&p2, g_p2);
    cudaGetSymbolAddress((void**)&p3, g_p3);
    cudaGetSymbolAddress((void**)&Ahi, g_Ahi);
    cudaGetSymbolAddress((void**)&Alo, g_Alo);
    cudaGetSymbolAddress((void**)&W0hi, g_W0hi);
    cudaGetSymbolAddress((void**)&W0lo, g_W0lo);
    cudaGetSymbolAddress((void**)&W1hi, g_W1hi);
    cudaGetSymbolAddress((void**)&W1lo, g_W1lo);
    cudaGetSymbolAddress((void**)&W2hi, g_W2hi);
    cudaGetSymbolAddress((void**)&W2lo, g_W2lo);

    cudaFuncSetAttribute(gemm_kernel<K0P/64>, cudaFuncAttributeMaxDynamicSharedMemorySize, GSMEM);
    cudaFuncSetAttribute(gemm_kernel<K1P/64>, cudaFuncAttributeMaxDynamicSharedMemorySize, GSMEM);

    dim3 gg(8, 8, 4);   // 256 CTAs, split-K=4

    convert_w<<<dim3(K1P*NOUT/2048, 1, 3), 256>>>(w0, b0, w1, b1, w2, b2);
    gate_prep_kernel<<<B_SZ, 256>>>(z, c, gw1, gb1, gw2, gb2, gw3, gb3, Ahi, Alo);
    gemm_kernel<K0P/64><<<gg, 256, GSMEM>>>(Ahi, Alo, W0hi, W0lo, p0, p1, p2, p3);

    prep_combine_kernel<<<B_SZ, 256>>>(z, p0, p1, p2, p3, Ahi, Alo);
    gemm_kernel<K1P/64><<<gg, 256, GSMEM>>>(Ahi, Alo, W1hi, W1lo, p0, p1, p2, p3);

    prep_combine_kernel<<<B_SZ, 256>>>(z, p0, p1, p2, p3, Ahi, Alo);
    gemm_kernel<K1P/64><<<gg, 256, GSMEM>>>(Ahi, Alo, W2hi, W2lo, p0, p1, p2, p3);

    combine_kernel<<<B_SZ*NOUT/1024, 256>>>(p0, p1, p2, p3, out);
}

// round 11
// speedup vs baseline: 1.3442x; 1.0321x over previous
#include <cuda_runtime.h>
#include <cuda_bf16.h>
#include <math.h>
#include <stdint.h>

#define B_SZ 1024
#define LATD 64
#define FCON 256
#define IN0  320
#define HIDD 512
#define INTER 576
#define NOUT 512
#define NE   8
#define GH   64
#define K0T  2560   // 8*320
#define K1T  4608   // 8*576

__device__ float g_coeff[B_SZ*NE];
__device__ float g_p0[B_SZ*NOUT];
__device__ float g_p1[B_SZ*NOUT];
__device__ float g_p2[B_SZ*NOUT];
__device__ float g_p3[B_SZ*NOUT];
// unscaled inputs, bf16 hi/lo
__device__ __nv_bfloat16 g_X0hi[B_SZ*IN0];
__device__ __nv_bfloat16 g_X0lo[B_SZ*IN0];
__device__ __nv_bfloat16 g_X1hi[B_SZ*INTER];
__device__ __nv_bfloat16 g_X1lo[B_SZ*INTER];
// weights [KTOT rows][512 cols], bf16 hi/lo (no bias tail)
__device__ __nv_bfloat16 g_W0hi[K0T*NOUT];
__device__ __nv_bfloat16 g_W0lo[K0T*NOUT];
__device__ __nv_bfloat16 g_W1hi[K1T*NOUT];
__device__ __nv_bfloat16 g_W1lo[K1T*NOUT];
__device__ __nv_bfloat16 g_W2hi[K1T*NOUT];
__device__ __nv_bfloat16 g_W2lo[K1T*NOUT];

__device__ __forceinline__ float elu_f(float x){ return x > 0.0f ? x : expm1f(x); }

__device__ __forceinline__ uint32_t smem_u32(const void* p){
    uint32_t a;
    asm("{ .reg .u64 t; cvta.to.shared.u64 t, %1; cvt.u32.u64 %0, t; }" : "=r"(a) : "l"(p));
    return a;
}

#define CP16(s, g) asm volatile("cp.async.cg.shared.global [%0], [%1], 16;" :: "r"(s), "l"(g))
#define CP_COMMIT() asm volatile("cp.async.commit_group;" ::: "memory")
#define CP_WAIT0()  asm volatile("cp.async.wait_group 0;" ::: "memory")

#define LDSM4(r0,r1,r2,r3,addr) \
    asm volatile("ldmatrix.sync.aligned.m8n8.x4.shared.b16 {%0,%1,%2,%3}, [%4];" \
        : "=r"(r0), "=r"(r1), "=r"(r2), "=r"(r3) : "r"(addr))

#define LDSM4T(r0,r1,r2,r3,addr) \
    asm volatile("ldmatrix.sync.aligned.m8n8.x4.trans.shared.b16 {%0,%1,%2,%3}, [%4];" \
        : "=r"(r0), "=r"(r1), "=r"(r2), "=r"(r3) : "r"(addr))

#define MMA16816(c, a0,a1,a2,a3, b0,b1) \
    asm volatile("mma.sync.aligned.m16n8k16.row.col.f32.bf16.bf16.f32 " \
        "{%0,%1,%2,%3}, {%4,%5,%6,%7}, {%8,%9}, {%0,%1,%2,%3};" \
        : "+f"((c)[0]), "+f"((c)[1]), "+f"((c)[2]), "+f"((c)[3]) \
        : "r"(a0), "r"(a1), "r"(a2), "r"(a3), "r"(b0), "r"(b1))

__device__ __forceinline__ void split_pair(float a, float b, uint32_t& h, uint32_t& l){
    __nv_bfloat16 ha = __float2bfloat16_rn(a), hb = __float2bfloat16_rn(b);
    __nv_bfloat16 la = __float2bfloat16_rn(a - __bfloat162float(ha));
    __nv_bfloat16 lb = __float2bfloat16_rn(b - __bfloat162float(hb));
    __nv_bfloat162 H = __halves2bfloat162(ha, hb), L = __halves2bfloat162(la, lb);
    h = *reinterpret_cast<uint32_t*>(&H); l = *reinterpret_cast<uint32_t*>(&L);
}

// ------- streaming W convert: fp32 [KTOT,512] -> bf16 hi/lo [KTOT,512] -------
__global__ __launch_bounds__(256) void convert_w(
    const float* __restrict__ w0, const float* __restrict__ w1, const float* __restrict__ w2)
{
    const float *W; __nv_bfloat16 *Whi, *Wlo; int KTOT;
    if (blockIdx.z == 0){ W=w0; Whi=g_W0hi; Wlo=g_W0lo; KTOT=K0T; }
    else if (blockIdx.z == 1){ W=w1; Whi=g_W1hi; Wlo=g_W1lo; KTOT=K1T; }
    else { W=w2; Whi=g_W2hi; Wlo=g_W2lo; KTOT=K1T; }

    size_t lin = (size_t)blockIdx.x*2048 + (size_t)threadIdx.x*8;
    if (lin >= (size_t)KTOT*NOUT) return;

    const float4* src = (const float4*)(W + lin);
    float4 x0 = src[0], x1 = src[1];
    uint4 hh, ll;
    split_pair(x0.x,x0.y,hh.x,ll.x); split_pair(x0.z,x0.w,hh.y,ll.y);
    split_pair(x1.x,x1.y,hh.z,ll.z); split_pair(x1.z,x1.w,hh.w,ll.w);
    *(uint4*)(Whi + lin) = hh;
    *(uint4*)(Wlo + lin) = ll;
}

// ---------------- gate + layer-0 input hi/lo (unscaled) ----------------
__global__ __launch_bounds__(256) void gate_prep_kernel(
    const float* __restrict__ z, const float* __restrict__ c,
    const float* __restrict__ gw1, const float* __restrict__ gb1,
    const float* __restrict__ gw2, const float* __restrict__ gb2,
    const float* __restrict__ gw3, const float* __restrict__ gb3)
{
    __shared__ float x[IN0], h1[GH], h2[GH], lg[NE];
    int b = blockIdx.x, tid = threadIdx.x;

    if (tid < LATD) x[tid] = z[b*LATD + tid];
    for (int i = tid; i < FCON; i += 256) x[LATD+i] = c[b*FCON + i];
    __syncthreads();

    if (tid < GH){
        float acc = gb1[tid];
        #pragma unroll 8
        for (int i = 0; i < IN0; i++) acc += x[i]*gw1[i*GH + tid];
        h1[tid] = elu_f(acc);
    }
    __syncthreads();
    if (tid < GH){
        float acc = gb2[tid];
        #pragma unroll 8
        for (int i = 0; i < GH; i++) acc += h1[i]*gw2[i*GH + tid];
        h2[tid] = elu_f(acc);
    }
    __syncthreads();
    if (tid < NE){
        float a = gb3[tid];
        #pragma unroll 8
        for (int i = 0; i < GH; i++) a += h2[i]*gw3[i*NE + tid];
        lg[tid] = a;
    }
    __syncthreads();
    if (tid < NE){
        float m = lg[0];
        #pragma unroll
        for (int i = 1; i < NE; i++) m = fmaxf(m, lg[i]);
        float s = 0.f;
        #pragma unroll
        for (int i = 0; i < NE; i++) s += expf(lg[i]-m);
        g_coeff[b*NE + tid] = expf(lg[tid]-m)/s;
    }

    // X0 = [z, c] unscaled, hi/lo; 320 elems = 40 uint4
    if (tid < 40){
        float v[8];
        #pragma unroll
        for (int l = 0; l < 8; l++) v[l] = x[tid*8 + l];
        uint4 hh, ll;
        split_pair(v[0],v[1],hh.x,ll.x); split_pair(v[2],v[3],hh.y,ll.y);
        split_pair(v[4],v[5],hh.z,ll.z); split_pair(v[6],v[7],hh.w,ll.w);
        ((uint4*)(g_X0hi + (size_t)b*IN0))[tid] = hh;
        ((uint4*)(g_X0lo + (size_t)b*IN0))[tid] = ll;
    }
}

// ------- prep for layers 1/2: X1 = [z | elu(sum_parts + coeff@bias)] hi/lo -------
__global__ __launch_bounds__(256) void prep_combine_kernel(
    const float* __restrict__ z,
    const float* __restrict__ p0, const float* __restrict__ p1,
    const float* __restrict__ p2, const float* __restrict__ p3,
    const float* __restrict__ bias)
{
    int b = blockIdx.x, tid = threadIdx.x;
    __shared__ float cf[NE];
    __shared__ float xp[INTER];
    if (tid < NE) cf[tid] = g_coeff[b*NE + tid];
    if (tid >= 8 && tid < 24){   // z part: 64 floats = 16 float4
        ((float4*)xp)[tid-8] = ((const float4*)(z + (size_t)b*LATD))[tid-8];
    }
    __syncthreads();

    const float4* a4 = (const float4*)(p0 + (size_t)b*NOUT);
    const float4* b4 = (const float4*)(p1 + (size_t)b*NOUT);
    const float4* c4 = (const float4*)(p2 + (size_t)b*NOUT);
    const float4* d4 = (const float4*)(p3 + (size_t)b*NOUT);
    for (int i = tid; i < NOUT/4; i += 256){
        float4 u = a4[i], w = b4[i], s = c4[i], t = d4[i];
        float r[4] = {u.x+w.x+s.x+t.x, u.y+w.y+s.y+t.y, u.z+w.z+s.z+t.z, u.w+w.w+s.w+t.w};
        #pragma unroll
        for (int l = 0; l < 4; l++){
            int o = i*4 + l;
            float bs = 0.f;
            #pragma unroll
            for (int e = 0; e < NE; e++) bs += cf[e]*bias[e*NOUT + o];
            xp[LATD + o] = elu_f(r[l] + bs);
        }
    }
    __syncthreads();

    // write 576 elems = 72 uint4
    if (tid < 72){
        float v[8];
        #pragma unroll
        for (int l = 0; l < 8; l++) v[l] = xp[tid*8 + l];
        uint4 hh, ll;
        split_pair(v[0],v[1],hh.x,ll.x); split_pair(v[2],v[3],hh.y,ll.y);
        split_pair(v[4],v[5],hh.z,ll.z); split_pair(v[6],v[7],hh.w,ll.w);
        ((uint4*)(g_X1hi + (size_t)b*INTER))[tid] = hh;
        ((uint4*)(g_X1lo + (size_t)b*INTER))[tid] = ll;
    }
}

// ------- final: out = sum_parts + coeff@bias -------
__global__ __launch_bounds__(128) void combine_kernel(
    const float* __restrict__ p0, const float* __restrict__ p1,
    const float* __restrict__ p2, const float* __restrict__ p3,
    const float* __restrict__ bias, float* __restrict__ out)
{
    int b = blockIdx.x, tid = threadIdx.x;
    __shared__ float cf[NE];
    if (tid < NE) cf[tid] = g_coeff[b*NE + tid];
    __syncthreads();

    size_t base = (size_t)b*NOUT;
    float4 u = ((const float4*)(p0+base))[tid];
    float4 w = ((const float4*)(p1+base))[tid];
    float4 s = ((const float4*)(p2+base))[tid];
    float4 t = ((const float4*)(p3+base))[tid];
    float r[4] = {u.x+w.x+s.x+t.x, u.y+w.y+s.y+t.y, u.z+w.z+s.z+t.z, u.w+w.w+s.w+t.w};
    #pragma unroll
    for (int l = 0; l < 4; l++){
        int o = tid*4 + l;
        float bs = 0.f;
        #pragma unroll
        for (int e = 0; e < NE; e++) bs += cf[e]*bias[e*NOUT + o];
        r[l] += bs;
    }
    float4 rr; rr.x=r[0]; rr.y=r[1]; rr.z=r[2]; rr.w=r[3];
    ((float4*)(out+base))[tid] = rr;
}

// ------- GEMM: expert-structured. CTA 128x64, warp 32x32 (4m x 2n).
// grid (8 n, 8 m, 4 e-split); each CTA: i-tiles outer (IN/64), 2 experts inner.
// out[b,o] += coeff[b,e] * (X[b, i-chunk] @ W[e-chunk, o])  via fresh acc2 + fp32 fold.
// smem: Ahi 2x16K @0, Alo 2x16K @32768, Bhi 2x8K @65536, Blo 2x8K @81920 = 96KB.
#define GSMEM 98304

template<int IN>
__global__ __launch_bounds__(256, 2) void gemm_kernel(
    const __nv_bfloat16* __restrict__ Xhi, const __nv_bfloat16* __restrict__ Xlo,
    const __nv_bfloat16* __restrict__ Whi, const __nv_bfloat16* __restrict__ Wlo,
    float* __restrict__ p0, float* __restrict__ p1,
    float* __restrict__ p2, float* __restrict__ p3)
{
    constexpr int ITILES = IN/64;
    constexpr int NCH = 2*ITILES;
    extern __shared__ char smem[];
    const uint32_t sb = smem_u32(smem);
    const int tid = threadIdx.x, wid = tid >> 5, L = tid & 31;
    const int m0 = blockIdx.y*128, n0 = blockIdx.x*64;
    const int wm = (wid & 3)*32, wn = (wid >> 2)*32;
    const int zz = blockIdx.z;
    const int e0 = zz*2;
    float* part = (zz == 0) ? p0 : (zz == 1) ? p1 : (zz == 2) ? p2 : p3;
    const int g = L >> 2;

    // A loader (128 rows x 128B)
    uint32_t s_oa[4];
    const __nv_bfloat16 *gxh[4], *gxl[4];
    #pragma unroll
    for (int r = 0; r < 4; r++){
        int ch = tid + r*256, row = ch >> 3, kc = ch & 7;
        s_oa[r] = row*128 + ((kc*16) ^ ((row & 7) << 4));
        gxh[r] = Xhi + (size_t)(m0+row)*IN + kc*8;
        gxl[r] = Xlo + (size_t)(m0+row)*IN + kc*8;
    }
    // B loader (64 k-rows x 128B of n)
    uint32_t s_ob[2];
    const __nv_bfloat16 *gwh[2], *gwl[2];
    #pragma unroll
    for (int r = 0; r < 2; r++){
        int ch = tid + r*256, row = ch >> 3, kc = ch & 7;
        s_ob[r] = row*128 + ((kc*16) ^ ((row & 7) << 4));
        gwh[r] = Whi + (size_t)row*NOUT + n0 + kc*8;
        gwl[r] = Wlo + (size_t)row*NOUT + n0 + kc*8;
    }

    // coeff regs: cfv[eo*4+q] = coeff[m0+wm+q*8+g, e0+eo]
    float cfv[8];
    #pragma unroll
    for (int eo = 0; eo < 2; eo++)
        #pragma unroll
        for (int qq = 0; qq < 4; qq++)
            cfv[eo*4+qq] = g_coeff[(size_t)(m0+wm+qq*8+g)*NE + e0 + eo];

    // fragment addressing
    const int alf = (L & 7) + ((L >> 3) & 1)*8;
    const int acb = (L >> 4)*16;
    const int axor = (alf & 7) << 4;
    const uint32_t arow0 = (uint32_t)(wm + alf)*128;
    const uint32_t arow1 = (uint32_t)(wm + 16 + alf)*128;
    const int mm = L >> 3, lr = L & 7;
    const uint32_t bconst = (uint32_t)(((mm & 1)*8 + lr)*128);
    const uint32_t bxor2 = (uint32_t)(lr << 4);
    const uint32_t bn0 = (uint32_t)((wn + (mm >> 1)*8)*2);

    float out_acc[2][4][4];
    #pragma unroll
    for (int i = 0; i < 2; i++)
        #pragma unroll
        for (int j = 0; j < 4; j++)
            #pragma unroll
            for (int c2 = 0; c2 < 4; c2++) out_acc[i][j][c2] = 0.0f;

#define ISSUE_A(ii) do { \
    uint32_t stA_ = sb + ((ii)&1)*16384; \
    size_t offA_ = (size_t)(ii)*64; \
    _Pragma("unroll") \
    for (int r = 0; r < 4; r++){ \
        CP16(stA_ + s_oa[r],         gxh[r] + offA_); \
        CP16(stA_ + 32768 + s_oa[r], gxl[r] + offA_); \
    } } while(0)

#define ISSUE_B(ii, ee, par) do { \
    uint32_t stB_ = sb + 65536 + (par)*8192; \
    size_t offB_ = (size_t)((ee)*IN + (ii)*64)*NOUT; \
    _Pragma("unroll") \
    for (int r = 0; r < 2; r++){ \
        CP16(stB_ + s_ob[r],         gwh[r] + offB_); \
        CP16(stB_ + 16384 + s_ob[r], gwl[r] + offB_); \
    } } while(0)

    // prologue: A0 + B(0, e0)
    ISSUE_A(0);
    ISSUE_B(0, e0, 0);
    CP_COMMIT();

    for (int c = 0; c < NCH; c++){
        CP_WAIT0();
        __syncthreads();

        if (c + 1 < NCH){
            int c1 = c + 1, i1 = c1 >> 1, eo1 = c1 & 1;
            ISSUE_B(i1, e0 + eo1, c1 & 1);
            if (eo1 == 1 && i1 + 1 < ITILES) ISSUE_A(i1 + 1);
            CP_COMMIT();
        }

        const uint32_t stA = sb + ((c >> 1) & 1)*16384;
        const uint32_t stB = sb + 65536 + (c & 1)*8192;

        float acc2[2][4][4];
        #pragma unroll
        for (int i = 0; i < 2; i++)
            #pragma unroll
            for (int j = 0; j < 4; j++)
                #pragma unroll
                for (int c2 = 0; c2 < 4; c2++) acc2[i][j][c2] = 0.0f;

        #pragma unroll
        for (int ks = 0; ks < 4; ks++){
            const uint32_t ca = (uint32_t)((ks*32 + acb) ^ axor);
            const uint32_t bk = (uint32_t)(ks*2048) + bconst;
            uint32_t a0[8], b0r[8];
            LDSM4(a0[0],a0[1],a0[2],a0[3], stA + arow0 + ca);
            LDSM4(a0[4],a0[5],a0[6],a0[7], stA + arow1 + ca);
            LDSM4T(b0r[0],b0r[1],b0r[2],b0r[3], stB + bk + (bn0 ^ bxor2));
            LDSM4T(b0r[4],b0r[5],b0r[6],b0r[7], stB + bk + ((bn0 + 32) ^ bxor2));
            #pragma unroll
            for (int i = 0; i < 2; i++)
                #pragma unroll
                for (int j = 0; j < 4; j++)
                    MMA16816(acc2[i][j], a0[i*4],a0[i*4+1],a0[i*4+2],a0[i*4+3], b0r[j*2],b0r[j*2+1]);

            uint32_t a1[8];
            LDSM4(a1[0],a1[1],a1[2],a1[3], stA + 32768 + arow0 + ca);
            LDSM4(a1[4],a1[5],a1[6],a1[7], stA + 32768 + arow1 + ca);
            #pragma unroll
            for (int i = 0; i < 2; i++)
                #pragma unroll
                for (int j = 0; j < 4; j++)
                    MMA16816(acc2[i][j], a1[i*4],a1[i*4+1],a1[i*4+2],a1[i*4+3], b0r[j*2],b0r[j*2+1]);

            uint32_t b1r[8];
            LDSM4T(b1r[0],b1r[1],b1r[2],b1r[3], stB + 16384 + bk + (bn0 ^ bxor2));
            LDSM4T(b1r[4],b1r[5],b1r[6],b1r[7], stB + 16384 + bk + ((bn0 + 32) ^ bxor2));
            #pragma unroll
            for (int i = 0; i < 2; i++)
                #pragma unroll
                for (int j = 0; j < 4; j++)
                    MMA16816(acc2[i][j], a0[i*4],a0[i*4+1],a0[i*4+2],a0[i*4+3], b1r[j*2],b1r[j*2+1]);
        }

        // fold: out += coeff[row, e] * acc2
        const float* cfp = cfv + (c & 1)*4;
        #pragma unroll
        for (int i = 0; i < 2; i++){
            float c0 = cfp[i*2], c1f = cfp[i*2+1];
            #pragma unroll
            for (int j = 0; j < 4; j++){
                out_acc[i][j][0] += c0  * acc2[i][j][0];
                out_acc[i][j][1] += c0  * acc2[i][j][1];
                out_acc[i][j][2] += c1f * acc2[i][j][2];
                out_acc[i][j][3] += c1f * acc2[i][j][3];
            }
        }
    }
#undef ISSUE_A
#undef ISSUE_B

    const int tg = L & 3;
    #pragma unroll
    for (int i = 0; i < 2; i++){
        #pragma unroll
        for (int j = 0; j < 4; j++){
            int row = m0 + wm + i*16 + g;
            int col = n0 + wn + j*8 + 2*tg;
            float2 v0, v1;
            v0.x = out_acc[i][j][0]; v0.y = out_acc[i][j][1];
            v1.x = out_acc[i][j][2]; v1.y = out_acc[i][j][3];
            *(float2*)(part + (size_t)row*NOUT + col) = v0;
            *(float2*)(part + (size_t)(row+8)*NOUT + col) = v1;
        }
    }
}

extern "C" void kernel_launch(void* const* d_in, const int* in_sizes, int n_in,
                              void* d_out, int out_size)
{
    const float* z   = (const float*)d_in[0];
    const float* c   = (const float*)d_in[1];
    const float* w0  = (const float*)d_in[2];
    const float* b0  = (const float*)d_in[3];
    const float* w1  = (const float*)d_in[4];
    const float* b1  = (const float*)d_in[5];
    const float* w2  = (const float*)d_in[6];
    const float* b2  = (const float*)d_in[7];
    const float* gw1 = (const float*)d_in[8];
    const float* gb1 = (const float*)d_in[9];
    const float* gw2 = (const float*)d_in[10];
    const float* gb2 = (const float*)d_in[11];
    const float* gw3 = (const float*)d_in[12];
    const float* gb3 = (const float*)d_in[13];
    float* out = (float*)d_out;

    float *p0, *p1, *p2, *p3;
    __nv_bfloat16 *X0hi, *X0lo, *X1hi, *X1lo;
    __nv_bfloat16 *W0hi, *W0lo, *W1hi, *W1lo, *W2hi, *W2lo;
    cudaGetSymbolAddress((void**)&p0, g_p0);
    cudaGetSymbolAddress((void**)&p1, g_p1);
    cudaGetSymbolAddress((void**)&p2, g_p2);
    cudaGetSymbolAddress((void**)&p3, g_p3);
    cudaGetSymbolAddress((void**)&X0hi, g_X0hi);
    cudaGetSymbolAddress((void**)&X0lo, g_X0lo);
    cudaGetSymbolAddress((void**)&X1hi, g_X1hi);
    cudaGetSymbolAddress((void**)&X1lo, g_X1lo);
    cudaGetSymbolAddress((void**)&W0hi, g_W0hi);
    cudaGetSymbolAddress((void**)&W0lo, g_W0lo);
    cudaGetSymbolAddress((void**)&W1hi, g_W1hi);
    cudaGetSymbolAddress((void**)&W1lo, g_W1lo);
    cudaGetSymbolAddress((void**)&W2hi, g_W2hi);
    cudaGetSymbolAddress((void**)&W2lo, g_W2lo);

    cudaFuncSetAttribute(gemm_kernel<IN0>,   cudaFuncAttributeMaxDynamicSharedMemorySize, GSMEM);
    cudaFuncSetAttribute(gemm_kernel<INTER>, cudaFuncAttributeMaxDynamicSharedMemorySize, GSMEM);

    dim3 gg(8, 8, 4);   // n-blocks, m-blocks, expert-split

    convert_w<<<dim3((K1T*NOUT)/2048, 1, 3), 256>>>(w0, w1, w2);
    gate_prep_kernel<<<B_SZ, 256>>>(z, c, gw1, gb1, gw2, gb2, gw3, gb3);
    gemm_kernel<IN0><<<gg, 256, GSMEM>>>(X0hi, X0lo, W0hi, W0lo, p0, p1, p2, p3);

    prep_combine_kernel<<<B_SZ, 256>>>(z, p0, p1, p2, p3, b0);
    gemm_kernel<INTER><<<gg, 256, GSMEM>>>(X1hi, X1lo, W1hi, W1lo, p0, p1, p2, p3);

    prep_combine_kernel<<<B_SZ, 256>>>(z, p0, p1, p2, p3, b1);
    gemm_kernel<INTER><<<gg, 256, GSMEM>>>(X1hi, X1lo, W2hi, W2lo, p0, p1, p2, p3);

    combine_kernel<<<B_SZ, 128>>>(p0, p1, p2, p3, b2, out);
}